// round 1
// baseline (speedup 1.0000x reference)
#include <cuda_runtime.h>

// ---------------- problem constants ----------------
#define NU   8039
#define NI   32770
#define NB   4771
#define NTOT (NU + NI + NB)        // 45580
#define EMB  32
#define NNZ  2000000
#define BATCH 2048
#define KB   100
#define EPSF    1e-8f
#define L2NORMF 1e-5f

// ---------------- static device scratch (no runtime alloc) ----------------
__device__ int   g_dv[NTOT];
__device__ int   g_de[NTOT];
__device__ float g_dvi[NTOT];
__device__ float g_dei[NTOT];
__device__ float g_z[NTOT * EMB];    // x * dvi
__device__ float g_u[NTOT * EMB];    // raw segsum, then scaled by dei in place
__device__ float g_v[NTOT * EMB];    // raw segsum
__device__ float g_emb[NTOT * EMB];  // final all_embeds

// fetch x[n][d] from the three concatenated feature tables
__device__ __forceinline__ float get_x(int n, int d,
                                       const float* __restrict__ uf,
                                       const float* __restrict__ itf,
                                       const float* __restrict__ bf) {
    if (n < NU)       return uf[n * EMB + d];
    if (n < NU + NI)  return itf[(n - NU) * EMB + d];
    return bf[(n - NU - NI) * EMB + d];
}

// ---------------- kernels ----------------

// zero degree counters, accumulators, and the loss output slot
__global__ void k_zero(float* __restrict__ loss_out) {
    int i = blockIdx.x * blockDim.x + threadIdx.x;
    int stride = gridDim.x * blockDim.x;
    for (int j = i; j < NTOT * EMB; j += stride) {
        g_u[j] = 0.0f;
        g_v[j] = 0.0f;
        if (j < NTOT) { g_dv[j] = 0; g_de[j] = 0; }
    }
    if (i == 0) *loss_out = 0.0f;
}

// degree histograms
__global__ void k_degrees(const int* __restrict__ rows, const int* __restrict__ cols) {
    int i = blockIdx.x * blockDim.x + threadIdx.x;
    if (i >= NNZ) return;
    atomicAdd(&g_dv[rows[i]], 1);
    atomicAdd(&g_de[cols[i]], 1);
}

// inverse sqrt degree factors
__global__ void k_inv() {
    int n = blockIdx.x * blockDim.x + threadIdx.x;
    if (n >= NTOT) return;
    g_dvi[n] = 1.0f / (sqrtf((float)g_dv[n]) + EPSF);
    g_dei[n] = 1.0f / (sqrtf((float)g_de[n]) + EPSF);
}

// z = x * dvi
__global__ void k_makez(const float* __restrict__ uf, const float* __restrict__ itf,
                        const float* __restrict__ bf) {
    int i = blockIdx.x * blockDim.x + threadIdx.x;
    if (i >= NTOT * EMB) return;
    int n = i >> 5, d = i & 31;
    g_z[i] = get_x(n, d, uf, itf, bf) * g_dvi[n];
}

// scatter pass 1: u[cols[e]] += z[rows[e]]   (float4 lanes: 8 threads/edge)
__global__ void k_scatter1(const int* __restrict__ rows, const int* __restrict__ cols) {
    long long i = (long long)blockIdx.x * blockDim.x + threadIdx.x;
    if (i >= (long long)NNZ * 8) return;
    int e = (int)(i >> 3);
    int q = (int)(i & 7);
    int r = __ldg(&rows[e]);
    int c = __ldg(&cols[e]);
    const float4* __restrict__ zsrc = (const float4*)g_z;
    float4 val = zsrc[r * 8 + q];
    atomicAdd(((float4*)g_u) + c * 8 + q, val);   // RED.128 (return discarded)
}

// u *= dei (in place)
__global__ void k_scaleu() {
    int i = blockIdx.x * blockDim.x + threadIdx.x;
    if (i >= NTOT * EMB) return;
    g_u[i] *= g_dei[i >> 5];
}

// scatter pass 2: v[rows[e]] += u_scaled[cols[e]]
__global__ void k_scatter2(const int* __restrict__ rows, const int* __restrict__ cols) {
    long long i = (long long)blockIdx.x * blockDim.x + threadIdx.x;
    if (i >= (long long)NNZ * 8) return;
    int e = (int)(i >> 3);
    int q = (int)(i & 7);
    int r = __ldg(&rows[e]);
    int c = __ldg(&cols[e]);
    const float4* __restrict__ usrc = (const float4*)g_u;
    float4 val = usrc[c * 8 + q];
    atomicAdd(((float4*)g_v) + r * 8 + q, val);
}

// final embeds + loss reduction: emb = x/2 + v*dvi/3 ; loss += L2NORM * sum(emb^2)
__global__ void k_final(const float* __restrict__ uf, const float* __restrict__ itf,
                        const float* __restrict__ bf, float* __restrict__ loss_out) {
    __shared__ float sred[8];
    int i = blockIdx.x * blockDim.x + threadIdx.x;
    float sq = 0.0f;
    if (i < NTOT * EMB) {
        int n = i >> 5, d = i & 31;
        float x = get_x(n, d, uf, itf, bf);
        float emb = 0.5f * x + (1.0f / 3.0f) * g_v[i] * g_dvi[n];
        g_emb[i] = emb;
        sq = emb * emb;
    }
    // block reduce
    #pragma unroll
    for (int o = 16; o; o >>= 1) sq += __shfl_xor_sync(0xffffffffu, sq, o);
    int lane = threadIdx.x & 31, w = threadIdx.x >> 5;
    if (lane == 0) sred[w] = sq;
    __syncthreads();
    if (w == 0) {
        float s = (lane < (blockDim.x >> 5)) ? sred[lane] : 0.0f;
        #pragma unroll
        for (int o = 4; o; o >>= 1) s += __shfl_xor_sync(0xffffffffu, s, o);
        if (lane == 0) atomicAdd(loss_out, s * L2NORMF);
    }
}

// scoring: one block per batch row; 4 warps split the 100 bundles
__global__ void k_score(const int* __restrict__ users, const int* __restrict__ bundles,
                        const float* __restrict__ ubound,
                        float* __restrict__ pred, float* __restrict__ bound) {
    __shared__ float ue[EMB];
    int b = blockIdx.x;
    int t = threadIdx.x;           // 128 threads
    int lane = t & 31, w = t >> 5;
    int uidx = users[b];           // users shape (BATCH, 1)
    if (t < EMB) ue[t] = g_emb[uidx * EMB + t];
    __syncthreads();
    float my_ue = ue[lane];
    for (int k = w; k < KB; k += 4) {
        int bi = bundles[b * KB + k];
        float p = my_ue * g_emb[(NU + NI + bi) * EMB + lane];
        #pragma unroll
        for (int o = 16; o; o >>= 1) p += __shfl_xor_sync(0xffffffffu, p, o);
        if (lane == 0) pred[b * KB + k] = p;
    }
    if (w == 0) {
        float p = my_ue * ubound[lane];   // user_bound shape (EMB, 1)
        #pragma unroll
        for (int o = 16; o; o >>= 1) p += __shfl_xor_sync(0xffffffffu, p, o);
        if (lane == 0) bound[b] = p;
    }
}

// ---------------- launch ----------------
extern "C" void kernel_launch(void* const* d_in, const int* in_sizes, int n_in,
                              void* d_out, int out_size) {
    const float* uf      = (const float*)d_in[0];
    const float* itf     = (const float*)d_in[1];
    const float* bf      = (const float*)d_in[2];
    const float* ubound  = (const float*)d_in[3];
    const int*   rows    = (const int*)d_in[4];
    const int*   cols    = (const int*)d_in[5];
    const int*   users   = (const int*)d_in[6];
    const int*   bundles = (const int*)d_in[7];

    float* out   = (float*)d_out;
    float* pred  = out;                       // BATCH*KB
    float* bound = out + BATCH * KB;          // BATCH
    float* loss  = out + BATCH * KB + BATCH;  // 1

    const int T = 256;
    const int nodeElems  = NTOT * EMB;                  // 1,458,560
    const int nodeBlocks = (nodeElems + T - 1) / T;

    k_zero<<<nodeBlocks, T>>>(loss);
    k_degrees<<<(NNZ + T - 1) / T, T>>>(rows, cols);
    k_inv<<<(NTOT + T - 1) / T, T>>>();
    k_makez<<<nodeBlocks, T>>>(uf, itf, bf);

    long long scatterThreads = (long long)NNZ * 8;
    int scatterBlocks = (int)((scatterThreads + T - 1) / T);
    k_scatter1<<<scatterBlocks, T>>>(rows, cols);
    k_scaleu<<<nodeBlocks, T>>>();
    k_scatter2<<<scatterBlocks, T>>>(rows, cols);

    k_final<<<nodeBlocks, T>>>(uf, itf, bf, loss);
    k_score<<<BATCH, 128>>>(users, bundles, ubound, pred, bound);
}